// round 2
// baseline (speedup 1.0000x reference)
#include <cuda_runtime.h>
#include <math.h>

#define NT 128
#define NB 512          // 65536 / 128
#define TSTEPS 128

static __device__ float g_partial[NB];
static __device__ unsigned int g_count = 0;

__device__ __forceinline__ float tanha(float x) {
    float y;
    asm("tanh.approx.f32 %0, %1;" : "=f"(y) : "f"(x));
    return y;
}
__device__ __forceinline__ float sigm(float x) {
    // sigmoid(x) = 0.5*tanh(x/2) + 0.5
    return fmaf(tanha(0.5f * x), 0.5f, 0.5f);
}

__global__ __launch_bounds__(NT)
void recdyn_kernel(const float* __restrict__ hist,   // (B,1,T,3)
                   const float* __restrict__ h0,     // (1,B,1)
                   const float* __restrict__ c0,     // (1,B,1)
                   const float* __restrict__ target, // (B,1,3)
                   const float* __restrict__ Wih,    // (4,3)
                   const float* __restrict__ Whh,    // (4,1)
                   const float* __restrict__ bih,    // (4)
                   const float* __restrict__ bhh,    // (4)
                   const float* __restrict__ Wm,     // (3,128)
                   const float* __restrict__ bm,     // (3)
                   const float* __restrict__ Wv,     // (6,128)
                   const float* __restrict__ bv,     // (6)
                   float* __restrict__ out)
{
    // head weights transposed: row t = [Wm0,Wm1,Wm2, Wv0..Wv5, pad x3]
    __shared__ float sw[TSTEPS * 12];
    __shared__ float sred[NT];
    __shared__ int slast;

    const int tid = threadIdx.x;

    #pragma unroll
    for (int i = tid; i < TSTEPS * 12; i += NT) {
        int t = i / 12, j = i % 12;
        float v = 0.0f;
        if (j < 3)      v = Wm[j * TSTEPS + t];
        else if (j < 9) v = Wv[(j - 3) * TSTEPS + t];
        sw[i] = v;
    }
    __syncthreads();

    const int b = blockIdx.x * NT + tid;
    const float* xb = hist + (size_t)b * (TSTEPS * 3);

    // ---- rotation matrix from last 3 timesteps ----
    float v1x = xb[127*3+0], v1y = xb[127*3+1], v1z = xb[127*3+2];
    float v2x = xb[126*3+0], v2y = xb[126*3+1], v2z = xb[126*3+2];
    float v3x = xb[125*3+0], v3y = xb[125*3+1], v3z = xb[125*3+2];

    float n1 = rsqrtf(v1x*v1x + v1y*v1y + v1z*v1z);
    float b1x = v1x*n1, b1y = v1y*n1, b1z = v1z*n1;

    float p  = v2x*b1x + v2y*b1y + v2z*b1z;
    float a2x = v2x - p*b1x, a2y = v2y - p*b1y, a2z = v2z - p*b1z;
    float n2 = rsqrtf(a2x*a2x + a2y*a2y + a2z*a2z);
    float b2x = a2x*n2, b2y = a2y*n2, b2z = a2z*n2;

    float b3x = b1y*b2z - b1z*b2y;
    float b3y = b1z*b2x - b1x*b2z;
    float b3z = b1x*b2y - b1y*b2x;

    float sgn = (v3x*b3x + v3y*b3y + v3z*b3z) > 0.0f ? 1.0f : -1.0f;
    float c3x = sgn*b3x, c3y = sgn*b3y, c3z = sgn*b3z;

    // ---- fold rotation into input weights ----
    float wih[12];
    #pragma unroll
    for (int k = 0; k < 12; ++k) wih[k] = Wih[k];
    float wp[4][3];
    #pragma unroll
    for (int k = 0; k < 4; ++k) {
        wp[k][0] = wih[k*3+0]*b1x + wih[k*3+1]*b2x + wih[k*3+2]*c3x;
        wp[k][1] = wih[k*3+0]*b1y + wih[k*3+1]*b2y + wih[k*3+2]*c3y;
        wp[k][2] = wih[k*3+0]*b1z + wih[k*3+1]*b2z + wih[k*3+2]*c3z;
    }
    float wh0 = Whh[0], wh1 = Whh[1], wh2 = Whh[2], wh3 = Whh[3];
    float bb0 = bih[0] + bhh[0];
    float bb1 = bih[1] + bhh[1];
    float bb2 = bih[2] + bhh[2];
    float bb3 = bih[3] + bhh[3];

    // ---- LSTM scan with on-the-fly head accumulation ----
    float h = h0[b], c = c0[b];
    float am0 = 0.f, am1 = 0.f, am2 = 0.f;
    float av0 = 0.f, av1 = 0.f, av2 = 0.f, av3 = 0.f, av4 = 0.f, av5 = 0.f;

    const float4* x4 = reinterpret_cast<const float4*>(xb);
    float4 qa = x4[0], qb = x4[1], qc = x4[2];

    for (int g = 0; g < 32; ++g) {
        float4 na, nb, nc;
        if (g < 31) { na = x4[g*3+3]; nb = x4[g*3+4]; nc = x4[g*3+5]; }
        float xs[12] = {qa.x, qa.y, qa.z, qa.w,
                        qb.x, qb.y, qb.z, qb.w,
                        qc.x, qc.y, qc.z, qc.w};
        #pragma unroll
        for (int k = 0; k < 4; ++k) {
            const int t = g*4 + k;
            float x0 = xs[3*k+0], x1 = xs[3*k+1], x2 = xs[3*k+2];

            // x-dependent gate parts (independent of h)
            float xp0 = fmaf(x0, wp[0][0], fmaf(x1, wp[0][1], fmaf(x2, wp[0][2], bb0)));
            float xp1 = fmaf(x0, wp[1][0], fmaf(x1, wp[1][1], fmaf(x2, wp[1][2], bb1)));
            float xp2 = fmaf(x0, wp[2][0], fmaf(x1, wp[2][1], fmaf(x2, wp[2][2], bb2)));
            float xp3 = fmaf(x0, wp[3][0], fmaf(x1, wp[3][1], fmaf(x2, wp[3][2], bb3)));

            float gi = fmaf(h, wh0, xp0);
            float gf = fmaf(h, wh1, xp1);
            float gg = fmaf(h, wh2, xp2);
            float go = fmaf(h, wh3, xp3);

            float si = sigm(gi);
            float sf = sigm(gf);
            float so = sigm(go);
            float tg = tanha(gg);

            c = fmaf(sf, c, si * tg);
            h = so * tanha(c);

            const float4* wrow = reinterpret_cast<const float4*>(&sw[t*12]);
            float4 w0 = wrow[0];
            float4 w1 = wrow[1];
            float  w8 = sw[t*12 + 8];

            am0 = fmaf(h, w0.x, am0);
            am1 = fmaf(h, w0.y, am1);
            am2 = fmaf(h, w0.z, am2);
            av0 = fmaf(h, w0.w, av0);
            av1 = fmaf(h, w1.x, av1);
            av2 = fmaf(h, w1.y, av2);
            av3 = fmaf(h, w1.z, av3);
            av4 = fmaf(h, w1.w, av4);
            av5 = fmaf(h, w8,   av5);
        }
        qa = na; qb = nb; qc = nc;
    }

    // ---- heads + gaussian NLL ----
    float m0 = am0 + bm[0], m1 = am1 + bm[1], m2 = am2 + bm[2];
    float e0 = av0 + bv[0], e1 = av1 + bv[1], e2 = av2 + bv[2];
    float e3 = av3 + bv[3], e4 = av4 + bv[4], e5 = av5 + bv[5];

    float tx = target[b*3+0], ty = target[b*3+1], tz = target[b*3+2];
    float rt0 = tx*b1x + ty*b1y + tz*b1z;
    float rt1 = tx*b2x + ty*b2y + tz*b2z;
    float rt2 = tx*c3x + ty*c3y + tz*c3z;

    float d0 = m0 - rt0, d1 = m1 - rt1, d2 = m2 - rt2;

    // quad = z^T D^{-1} z with z = L^{-1} d (forward substitution)
    float z0 = d0;
    float z1 = d1 - e0 * z0;
    float z2 = d2 - e1 * z0 - e2 * z1;

    float quad = z0*z0*__expf(-e3) + z1*z1*__expf(-e4) + z2*z2*__expf(-e5);
    float val = 0.5f * (__expf(e3) + __expf(e4) + __expf(e5) + quad);

    // ---- block tree reduction (deterministic) ----
    sred[tid] = val;
    __syncthreads();
    #pragma unroll
    for (int off = NT/2; off > 0; off >>= 1) {
        if (tid < off) sred[tid] += sred[tid + off];
        __syncthreads();
    }

    // ---- last-block grid reduction (deterministic fixed-order) ----
    if (tid == 0) {
        g_partial[blockIdx.x] = sred[0];
        __threadfence();
        unsigned int n = atomicAdd(&g_count, 1u);
        slast = (n == NB - 1) ? 1 : 0;
    }
    __syncthreads();

    if (slast) {
        // 128 threads each sum 4 partials in fixed index order
        float s = 0.0f;
        #pragma unroll
        for (int k = 0; k < 4; ++k)
            s += __ldcg(&g_partial[tid * 4 + k]);
        sred[tid] = s;
        __syncthreads();
        #pragma unroll
        for (int off = NT/2; off > 0; off >>= 1) {
            if (tid < off) sred[tid] += sred[tid + off];
            __syncthreads();
        }
        if (tid == 0) {
            out[0] = sred[0] * (1.0f / 65536.0f);
            g_count = 0;   // reset for next (graph-replayed) launch
        }
    }
}

extern "C" void kernel_launch(void* const* d_in, const int* in_sizes, int n_in,
                              void* d_out, int out_size)
{
    const float* hist   = (const float*)d_in[0];
    const float* h0     = (const float*)d_in[1];
    const float* c0     = (const float*)d_in[2];
    const float* target = (const float*)d_in[3];
    const float* Wih    = (const float*)d_in[4];
    const float* Whh    = (const float*)d_in[5];
    const float* bih    = (const float*)d_in[6];
    const float* bhh    = (const float*)d_in[7];
    const float* Wm     = (const float*)d_in[8];
    const float* bm     = (const float*)d_in[9];
    const float* Wv     = (const float*)d_in[10];
    const float* bv     = (const float*)d_in[11];

    recdyn_kernel<<<NB, NT>>>(hist, h0, c0, target,
                              Wih, Whh, bih, bhh, Wm, bm, Wv, bv,
                              (float*)d_out);
}

// round 3
// speedup vs baseline: 1.2520x; 1.2520x over previous
#include <cuda_runtime.h>
#include <math.h>
#include <stdint.h>

#define NT      128
#define NB      512            // 65536 / NT
#define TSTEPS  128
#define TT      32             // timesteps per tile
#define NTILES  4              // TSTEPS / TT
#define ROWF    99             // 96 floats + 3 pad -> conflict-free LDS (3*tid mod 32 bijective)
#define TILEF   (NT * ROWF)    // floats per tile buffer (12672)

// dynamic smem layout (floats): [ sw:1536 | sred:128 | buf0:TILEF | buf1:TILEF ]
#define SW_OFF   0
#define SRED_OFF 1536
#define BUF_OFF  1664
#define SMEM_FLOATS (BUF_OFF + 2 * TILEF)
#define SMEM_BYTES  (SMEM_FLOATS * 4)

static __device__ float g_partial[NB];
static __device__ unsigned int g_count = 0;

__device__ __forceinline__ float tanha(float x) {
    float y;
    asm("tanh.approx.f32 %0, %1;" : "=f"(y) : "f"(x));
    return y;
}
__device__ __forceinline__ float sigm(float x) {
    return fmaf(tanha(0.5f * x), 0.5f, 0.5f);   // sigmoid(x) = 0.5*tanh(x/2)+0.5
}
__device__ __forceinline__ void cp_async4(uint32_t dst, const float* src) {
    asm volatile("cp.async.ca.shared.global [%0], [%1], 4;" :: "r"(dst), "l"(src));
}

__global__ __launch_bounds__(NT)
void recdyn_kernel(const float* __restrict__ hist,   // (B,1,T,3)
                   const float* __restrict__ h0,     // (1,B,1)
                   const float* __restrict__ c0,     // (1,B,1)
                   const float* __restrict__ target, // (B,1,3)
                   const float* __restrict__ Wih,    // (4,3)
                   const float* __restrict__ Whh,    // (4,1)
                   const float* __restrict__ bih,    // (4)
                   const float* __restrict__ bhh,    // (4)
                   const float* __restrict__ Wm,     // (3,128)
                   const float* __restrict__ bm,     // (3)
                   const float* __restrict__ Wv,     // (6,128)
                   const float* __restrict__ bv,     // (6)
                   float* __restrict__ out)
{
    extern __shared__ float smem[];
    float* sw   = smem + SW_OFF;    // head weights, transposed: row t = [Wm0..2, Wv0..5, pad3]
    float* sred = smem + SRED_OFF;
    float* sbuf = smem + BUF_OFF;
    __shared__ int slast;

    const int tid = threadIdx.x;
    const int b   = blockIdx.x * NT + tid;

    // ---- stage head weights ----
    for (int i = tid; i < TSTEPS * 12; i += NT) {
        int t = i / 12, j = i % 12;
        float v = 0.0f;
        if (j < 3)      v = Wm[j * TSTEPS + t];
        else if (j < 9) v = Wv[(j - 3) * TSTEPS + t];
        sw[i] = v;
    }

    // ---- kick off cp.async staging of tile 0 ----
    const float* gblk = hist + (size_t)blockIdx.x * NT * (TSTEPS * 3);
    uint32_t sbuf_u32 = (uint32_t)__cvta_generic_to_shared(sbuf);
    {
        const float* gsrc = gblk;            // tile 0 offset
        uint32_t dst0 = sbuf_u32;            // buf0
        #pragma unroll 4
        for (int i = tid; i < NT * 96; i += NT) {
            int seg = i / 96;
            int j   = i - seg * 96;
            cp_async4(dst0 + (uint32_t)(seg * ROWF + j) * 4u,
                      gsrc + (size_t)seg * (TSTEPS * 3) + j);
        }
        asm volatile("cp.async.commit_group;");
    }

    // ---- rotation matrix from last 3 timesteps (direct LDG; warms L2 for tile 3) ----
    const float4* xr = reinterpret_cast<const float4*>(hist + (size_t)b * (TSTEPS * 3));
    float4 r93 = xr[93];   // floats 372..375  (t124 f0..f2, t125 f0)
    float4 r94 = xr[94];   // floats 376..379  (t125 f1,f2, t126 f0,f1)
    float4 r95 = xr[95];   // floats 380..383  (t126 f2, t127 f0..f2)

    float v1x = r95.y, v1y = r95.z, v1z = r95.w;   // t = 127
    float v2x = r94.z, v2y = r94.w, v2z = r95.x;   // t = 126
    float v3x = r93.w, v3y = r94.x, v3z = r94.y;   // t = 125

    float n1 = rsqrtf(v1x*v1x + v1y*v1y + v1z*v1z);
    float b1x = v1x*n1, b1y = v1y*n1, b1z = v1z*n1;

    float p  = v2x*b1x + v2y*b1y + v2z*b1z;
    float a2x = v2x - p*b1x, a2y = v2y - p*b1y, a2z = v2z - p*b1z;
    float n2 = rsqrtf(a2x*a2x + a2y*a2y + a2z*a2z);
    float b2x = a2x*n2, b2y = a2y*n2, b2z = a2z*n2;

    float b3x = b1y*b2z - b1z*b2y;
    float b3y = b1z*b2x - b1x*b2z;
    float b3z = b1x*b2y - b1y*b2x;

    float sgn = (v3x*b3x + v3y*b3y + v3z*b3z) > 0.0f ? 1.0f : -1.0f;
    float c3x = sgn*b3x, c3y = sgn*b3y, c3z = sgn*b3z;

    // ---- fold rotation into input weights ----
    float wih[12];
    #pragma unroll
    for (int k = 0; k < 12; ++k) wih[k] = Wih[k];
    float wp[4][3];
    #pragma unroll
    for (int k = 0; k < 4; ++k) {
        wp[k][0] = wih[k*3+0]*b1x + wih[k*3+1]*b2x + wih[k*3+2]*c3x;
        wp[k][1] = wih[k*3+0]*b1y + wih[k*3+1]*b2y + wih[k*3+2]*c3y;
        wp[k][2] = wih[k*3+0]*b1z + wih[k*3+1]*b2z + wih[k*3+2]*c3z;
    }
    float wh0 = Whh[0], wh1 = Whh[1], wh2 = Whh[2], wh3 = Whh[3];
    float bb0 = bih[0] + bhh[0];
    float bb1 = bih[1] + bhh[1];
    float bb2 = bih[2] + bhh[2];
    float bb3 = bih[3] + bhh[3];

    // ---- LSTM scan over 4 double-buffered tiles ----
    float h = h0[b], c = c0[b];
    float am0 = 0.f, am1 = 0.f, am2 = 0.f;
    float av0 = 0.f, av1 = 0.f, av2 = 0.f, av3 = 0.f, av4 = 0.f, av5 = 0.f;

    for (int g = 0; g < NTILES; ++g) {
        // issue next tile into the other buffer, then wait for current tile
        if (g + 1 < NTILES) {
            const float* gsrc = gblk + (size_t)(g + 1) * 96;
            uint32_t dstb = sbuf_u32 + (uint32_t)(((g + 1) & 1) * TILEF) * 4u;
            #pragma unroll 4
            for (int i = tid; i < NT * 96; i += NT) {
                int seg = i / 96;
                int j   = i - seg * 96;
                cp_async4(dstb + (uint32_t)(seg * ROWF + j) * 4u,
                          gsrc + (size_t)seg * (TSTEPS * 3) + j);
            }
            asm volatile("cp.async.commit_group;");
            asm volatile("cp.async.wait_group 1;");
        } else {
            asm volatile("cp.async.wait_group 0;");
        }
        __syncthreads();

        const float* row = sbuf + (g & 1) * TILEF + tid * ROWF;
        const float* swt = sw + g * TT * 12;

        for (int tb = 0; tb < TT; tb += 4) {
            #pragma unroll
            for (int k = 0; k < 4; ++k) {
                const int tl = tb + k;
                float x0 = row[tl*3 + 0];
                float x1 = row[tl*3 + 1];
                float x2 = row[tl*3 + 2];

                float xp0 = fmaf(x0, wp[0][0], fmaf(x1, wp[0][1], fmaf(x2, wp[0][2], bb0)));
                float xp1 = fmaf(x0, wp[1][0], fmaf(x1, wp[1][1], fmaf(x2, wp[1][2], bb1)));
                float xp2 = fmaf(x0, wp[2][0], fmaf(x1, wp[2][1], fmaf(x2, wp[2][2], bb2)));
                float xp3 = fmaf(x0, wp[3][0], fmaf(x1, wp[3][1], fmaf(x2, wp[3][2], bb3)));

                float gi = fmaf(h, wh0, xp0);
                float gf = fmaf(h, wh1, xp1);
                float gg = fmaf(h, wh2, xp2);
                float go = fmaf(h, wh3, xp3);

                float si = sigm(gi);
                float sf = sigm(gf);
                float so = sigm(go);
                float tg = tanha(gg);

                c = fmaf(sf, c, si * tg);
                h = so * tanha(c);

                const float4* wrow = reinterpret_cast<const float4*>(swt + tl * 12);
                float4 w0 = wrow[0];
                float4 w1 = wrow[1];
                float  w8 = (swt + tl * 12)[8];

                am0 = fmaf(h, w0.x, am0);
                am1 = fmaf(h, w0.y, am1);
                am2 = fmaf(h, w0.z, am2);
                av0 = fmaf(h, w0.w, av0);
                av1 = fmaf(h, w1.x, av1);
                av2 = fmaf(h, w1.y, av2);
                av3 = fmaf(h, w1.z, av3);
                av4 = fmaf(h, w1.w, av4);
                av5 = fmaf(h, w8,   av5);
            }
        }
        __syncthreads();
    }

    // ---- heads + gaussian NLL ----
    float m0 = am0 + bm[0], m1 = am1 + bm[1], m2 = am2 + bm[2];
    float e0 = av0 + bv[0], e1 = av1 + bv[1], e2 = av2 + bv[2];
    float e3 = av3 + bv[3], e4 = av4 + bv[4], e5 = av5 + bv[5];

    float tx = target[b*3+0], ty = target[b*3+1], tz = target[b*3+2];
    float rt0 = tx*b1x + ty*b1y + tz*b1z;
    float rt1 = tx*b2x + ty*b2y + tz*b2z;
    float rt2 = tx*c3x + ty*c3y + tz*c3z;

    float d0 = m0 - rt0, d1 = m1 - rt1, d2 = m2 - rt2;

    // quad = z^T D^{-1} z with z = L^{-1} d
    float z0 = d0;
    float z1 = d1 - e0 * z0;
    float z2 = d2 - e1 * z0 - e2 * z1;

    float quad = z0*z0*__expf(-e3) + z1*z1*__expf(-e4) + z2*z2*__expf(-e5);
    float val = 0.5f * (__expf(e3) + __expf(e4) + __expf(e5) + quad);

    // ---- block tree reduction (deterministic) ----
    sred[tid] = val;
    __syncthreads();
    #pragma unroll
    for (int off = NT/2; off > 0; off >>= 1) {
        if (tid < off) sred[tid] += sred[tid + off];
        __syncthreads();
    }

    // ---- last-block grid reduction (deterministic fixed order) ----
    if (tid == 0) {
        g_partial[blockIdx.x] = sred[0];
        __threadfence();
        unsigned int n = atomicAdd(&g_count, 1u);
        slast = (n == NB - 1) ? 1 : 0;
    }
    __syncthreads();

    if (slast) {
        float s = 0.0f;
        #pragma unroll
        for (int k = 0; k < 4; ++k)
            s += __ldcg(&g_partial[tid * 4 + k]);
        sred[tid] = s;
        __syncthreads();
        #pragma unroll
        for (int off = NT/2; off > 0; off >>= 1) {
            if (tid < off) sred[tid] += sred[tid + off];
            __syncthreads();
        }
        if (tid == 0) {
            out[0] = sred[0] * (1.0f / 65536.0f);
            g_count = 0;   // reset for next graph replay
        }
    }
}

extern "C" void kernel_launch(void* const* d_in, const int* in_sizes, int n_in,
                              void* d_out, int out_size)
{
    const float* hist   = (const float*)d_in[0];
    const float* h0     = (const float*)d_in[1];
    const float* c0     = (const float*)d_in[2];
    const float* target = (const float*)d_in[3];
    const float* Wih    = (const float*)d_in[4];
    const float* Whh    = (const float*)d_in[5];
    const float* bih    = (const float*)d_in[6];
    const float* bhh    = (const float*)d_in[7];
    const float* Wm     = (const float*)d_in[8];
    const float* bm     = (const float*)d_in[9];
    const float* Wv     = (const float*)d_in[10];
    const float* bv     = (const float*)d_in[11];

    cudaFuncSetAttribute(recdyn_kernel,
                         cudaFuncAttributeMaxDynamicSharedMemorySize, SMEM_BYTES);

    recdyn_kernel<<<NB, NT, SMEM_BYTES>>>(hist, h0, c0, target,
                                          Wih, Whh, bih, bhh, Wm, bm, Wv, bv,
                                          (float*)d_out);
}

// round 4
// speedup vs baseline: 1.8049x; 1.4415x over previous
#include <cuda_runtime.h>
#include <math.h>
#include <stdint.h>

#define NT      64
#define NB      1024           // 65536 / NT
#define TSTEPS  128
#define TT      8              // timesteps per tile
#define NTILES  16             // TSTEPS / TT
#define ROW4    7              // float4s per smem row (6 data + 1 pad); gcd(7,8)=1 -> conflict-free
#define TILE4   (NT * ROW4)    // float4s per tile buffer (448)
#define TILEF   (TILE4 * 4)    // floats per tile buffer (1792)

static __device__ float g_partial[NB];
static __device__ unsigned int g_count = 0;

__device__ __forceinline__ float tanha(float x) {
    float y;
    asm("tanh.approx.f32 %0, %1;" : "=f"(y) : "f"(x));
    return y;
}
__device__ __forceinline__ float sigm(float x) {
    return fmaf(tanha(0.5f * x), 0.5f, 0.5f);   // sigmoid(x) = 0.5*tanh(x/2)+0.5
}
__device__ __forceinline__ void cp_async16(uint32_t dst, const float4* src) {
    asm volatile("cp.async.cg.shared.global [%0], [%1], 16;" :: "r"(dst), "l"(src));
}

__global__ __launch_bounds__(NT)
void recdyn_kernel(const float* __restrict__ hist,   // (B,1,T,3)
                   const float* __restrict__ h0,     // (1,B,1)
                   const float* __restrict__ c0,     // (1,B,1)
                   const float* __restrict__ target, // (B,1,3)
                   const float* __restrict__ Wih,    // (4,3)
                   const float* __restrict__ Whh,    // (4,1)
                   const float* __restrict__ bih,    // (4)
                   const float* __restrict__ bhh,    // (4)
                   const float* __restrict__ Wm,     // (3,128)
                   const float* __restrict__ bm,     // (3)
                   const float* __restrict__ Wv,     // (6,128)
                   const float* __restrict__ bv,     // (6)
                   float* __restrict__ out)
{
    __shared__ float sw[TSTEPS * 12];     // head weights: row t = [Wm0..2, Wv0..5, pad3]
    __shared__ float sred[NT];
    __shared__ float sbuf[2 * TILEF];     // double-buffered x tiles
    __shared__ int slast;

    const int tid = threadIdx.x;
    const int b   = blockIdx.x * NT + tid;

    // ---- stage head weights (transposed) ----
    for (int i = tid; i < TSTEPS * 12; i += NT) {
        int t = i / 12, j = i % 12;
        float v = 0.0f;
        if (j < 3)      v = Wm[j * TSTEPS + t];
        else if (j < 9) v = Wv[(j - 3) * TSTEPS + t];
        sw[i] = v;
    }

    // ---- cp.async (seg,q) walk setup: i = tid + 64k over 384 f4 slots, seg=i/6, q=i%6 ----
    const int seg0 = tid / 6;
    const int q0   = tid - seg0 * 6;
    const float4* gbase = reinterpret_cast<const float4*>(hist) + (size_t)blockIdx.x * NT * 96;
    const uint32_t sbuf_u32 = (uint32_t)__cvta_generic_to_shared(sbuf);

    // ---- kick off tile 0 ----
    {
        int s = seg0, qq = q0;
        #pragma unroll
        for (int k = 0; k < 6; ++k) {
            cp_async16(sbuf_u32 + (uint32_t)(s * ROW4 + qq) * 16u,
                       gbase + (size_t)s * 96 + qq);
            s += 10; qq += 4; if (qq >= 6) { qq -= 6; ++s; }
        }
        asm volatile("cp.async.commit_group;");
    }

    // ---- rotation matrix from last 3 timesteps (direct LDG) ----
    const float4* xr = reinterpret_cast<const float4*>(hist + (size_t)b * (TSTEPS * 3));
    float4 r93 = xr[93];
    float4 r94 = xr[94];
    float4 r95 = xr[95];

    float v1x = r95.y, v1y = r95.z, v1z = r95.w;   // t = 127
    float v2x = r94.z, v2y = r94.w, v2z = r95.x;   // t = 126
    float v3x = r93.w, v3y = r94.x, v3z = r94.y;   // t = 125

    float n1 = rsqrtf(v1x*v1x + v1y*v1y + v1z*v1z);
    float b1x = v1x*n1, b1y = v1y*n1, b1z = v1z*n1;

    float p  = v2x*b1x + v2y*b1y + v2z*b1z;
    float a2x = v2x - p*b1x, a2y = v2y - p*b1y, a2z = v2z - p*b1z;
    float n2 = rsqrtf(a2x*a2x + a2y*a2y + a2z*a2z);
    float b2x = a2x*n2, b2y = a2y*n2, b2z = a2z*n2;

    float b3x = b1y*b2z - b1z*b2y;
    float b3y = b1z*b2x - b1x*b2z;
    float b3z = b1x*b2y - b1y*b2x;

    float sgn = (v3x*b3x + v3y*b3y + v3z*b3z) > 0.0f ? 1.0f : -1.0f;
    float c3x = sgn*b3x, c3y = sgn*b3y, c3z = sgn*b3z;

    // ---- fold rotation into input weights ----
    float wih[12];
    #pragma unroll
    for (int k = 0; k < 12; ++k) wih[k] = Wih[k];
    float wp[4][3];
    #pragma unroll
    for (int k = 0; k < 4; ++k) {
        wp[k][0] = wih[k*3+0]*b1x + wih[k*3+1]*b2x + wih[k*3+2]*c3x;
        wp[k][1] = wih[k*3+0]*b1y + wih[k*3+1]*b2y + wih[k*3+2]*c3y;
        wp[k][2] = wih[k*3+0]*b1z + wih[k*3+1]*b2z + wih[k*3+2]*c3z;
    }
    float wh0 = Whh[0], wh1 = Whh[1], wh2 = Whh[2], wh3 = Whh[3];
    float bb0 = bih[0] + bhh[0];
    float bb1 = bih[1] + bhh[1];
    float bb2 = bih[2] + bhh[2];
    float bb3 = bih[3] + bhh[3];

    // ---- LSTM scan over 16 double-buffered tiles ----
    float h = h0[b], c = c0[b];
    float am0 = 0.f, am1 = 0.f, am2 = 0.f;
    float av0 = 0.f, av1 = 0.f, av2 = 0.f, av3 = 0.f, av4 = 0.f, av5 = 0.f;

    for (int g = 0; g < NTILES; ++g) {
        if (g + 1 < NTILES) {
            uint32_t dstb = sbuf_u32 + (uint32_t)(((g + 1) & 1) * TILEF) * 4u;
            const float4* src = gbase + (g + 1) * 6;
            int s = seg0, qq = q0;
            #pragma unroll
            for (int k = 0; k < 6; ++k) {
                cp_async16(dstb + (uint32_t)(s * ROW4 + qq) * 16u,
                           src + (size_t)s * 96 + qq);
                s += 10; qq += 4; if (qq >= 6) { qq -= 6; ++s; }
            }
            asm volatile("cp.async.commit_group;");
            asm volatile("cp.async.wait_group 1;");
        } else {
            asm volatile("cp.async.wait_group 0;");
        }
        __syncthreads();

        const float4* brow = reinterpret_cast<const float4*>(sbuf + (g & 1) * TILEF) + tid * ROW4;
        const float* swt = sw + g * TT * 12;

        #pragma unroll
        for (int half = 0; half < 2; ++half) {
            float4 p0 = brow[half*3 + 0];
            float4 p1 = brow[half*3 + 1];
            float4 p2 = brow[half*3 + 2];
            float xs[12] = {p0.x, p0.y, p0.z, p0.w,
                            p1.x, p1.y, p1.z, p1.w,
                            p2.x, p2.y, p2.z, p2.w};
            #pragma unroll
            for (int k = 0; k < 4; ++k) {
                const int tl = half * 4 + k;
                float x0 = xs[3*k+0], x1 = xs[3*k+1], x2 = xs[3*k+2];

                float xp0 = fmaf(x0, wp[0][0], fmaf(x1, wp[0][1], fmaf(x2, wp[0][2], bb0)));
                float xp1 = fmaf(x0, wp[1][0], fmaf(x1, wp[1][1], fmaf(x2, wp[1][2], bb1)));
                float xp2 = fmaf(x0, wp[2][0], fmaf(x1, wp[2][1], fmaf(x2, wp[2][2], bb2)));
                float xp3 = fmaf(x0, wp[3][0], fmaf(x1, wp[3][1], fmaf(x2, wp[3][2], bb3)));

                float gi = fmaf(h, wh0, xp0);
                float gf = fmaf(h, wh1, xp1);
                float gg = fmaf(h, wh2, xp2);
                float go = fmaf(h, wh3, xp3);

                float si = sigm(gi);
                float sf = sigm(gf);
                float so = sigm(go);
                float tg = tanha(gg);

                c = fmaf(sf, c, si * tg);
                h = so * tanha(c);

                const float* wr = swt + tl * 12;
                const float4* wv4 = reinterpret_cast<const float4*>(wr);
                float4 w0 = wv4[0];
                float4 w1 = wv4[1];
                float  w8 = wr[8];

                am0 = fmaf(h, w0.x, am0);
                am1 = fmaf(h, w0.y, am1);
                am2 = fmaf(h, w0.z, am2);
                av0 = fmaf(h, w0.w, av0);
                av1 = fmaf(h, w1.x, av1);
                av2 = fmaf(h, w1.y, av2);
                av3 = fmaf(h, w1.z, av3);
                av4 = fmaf(h, w1.w, av4);
                av5 = fmaf(h, w8,   av5);
            }
        }
        __syncthreads();
    }

    // ---- heads + gaussian NLL ----
    float m0 = am0 + bm[0], m1 = am1 + bm[1], m2 = am2 + bm[2];
    float e0 = av0 + bv[0], e1 = av1 + bv[1], e2 = av2 + bv[2];
    float e3 = av3 + bv[3], e4 = av4 + bv[4], e5 = av5 + bv[5];

    float tx = target[b*3+0], ty = target[b*3+1], tz = target[b*3+2];
    float rt0 = tx*b1x + ty*b1y + tz*b1z;
    float rt1 = tx*b2x + ty*b2y + tz*b2z;
    float rt2 = tx*c3x + ty*c3y + tz*c3z;

    float d0 = m0 - rt0, d1 = m1 - rt1, d2 = m2 - rt2;

    // quad = z^T D^{-1} z with z = L^{-1} d
    float z0 = d0;
    float z1 = d1 - e0 * z0;
    float z2 = d2 - e1 * z0 - e2 * z1;

    float quad = z0*z0*__expf(-e3) + z1*z1*__expf(-e4) + z2*z2*__expf(-e5);
    float val = 0.5f * (__expf(e3) + __expf(e4) + __expf(e5) + quad);

    // ---- block tree reduction (deterministic) ----
    sred[tid] = val;
    __syncthreads();
    #pragma unroll
    for (int off = NT/2; off > 0; off >>= 1) {
        if (tid < off) sred[tid] += sred[tid + off];
        __syncthreads();
    }

    // ---- last-block grid reduction (deterministic fixed order) ----
    if (tid == 0) {
        g_partial[blockIdx.x] = sred[0];
        __threadfence();
        unsigned int n = atomicAdd(&g_count, 1u);
        slast = (n == NB - 1) ? 1 : 0;
    }
    __syncthreads();

    if (slast) {
        float s = 0.0f;
        #pragma unroll
        for (int k = 0; k < NB / NT; ++k)
            s += __ldcg(&g_partial[tid * (NB / NT) + k]);
        sred[tid] = s;
        __syncthreads();
        #pragma unroll
        for (int off = NT/2; off > 0; off >>= 1) {
            if (tid < off) sred[tid] += sred[tid + off];
            __syncthreads();
        }
        if (tid == 0) {
            out[0] = sred[0] * (1.0f / 65536.0f);
            g_count = 0;   // reset for next graph replay
        }
    }
}

extern "C" void kernel_launch(void* const* d_in, const int* in_sizes, int n_in,
                              void* d_out, int out_size)
{
    const float* hist   = (const float*)d_in[0];
    const float* h0     = (const float*)d_in[1];
    const float* c0     = (const float*)d_in[2];
    const float* target = (const float*)d_in[3];
    const float* Wih    = (const float*)d_in[4];
    const float* Whh    = (const float*)d_in[5];
    const float* bih    = (const float*)d_in[6];
    const float* bhh    = (const float*)d_in[7];
    const float* Wm     = (const float*)d_in[8];
    const float* bm     = (const float*)d_in[9];
    const float* Wv     = (const float*)d_in[10];
    const float* bv     = (const float*)d_in[11];

    recdyn_kernel<<<NB, NT>>>(hist, h0, c0, target,
                              Wih, Whh, bih, bhh, Wm, bm, Wv, bv,
                              (float*)d_out);
}